// round 1
// baseline (speedup 1.0000x reference)
#include <cuda_runtime.h>

#define T_OBS   8
#define T_PRE   12
#define BATCH   524288
#define HID     8
#define GATES   32
#define WSTRIDE 12                   // u64 slots per gate: w0,w1,b,pad, whh[0..7]
#define LSTM_U64 (GATES * WSTRIDE)   // 384
#define TOT_U64  (2 * LSTM_U64)      // 768

typedef unsigned long long u64;

// Fused, pair-duplicated weights: [lstm][gate][12 u64]
__device__ u64 g_fw[TOT_U64];

__device__ __forceinline__ u64 dupf(float w) {
    unsigned int u = __float_as_uint(w);
    return ((u64)u << 32) | (u64)u;
}

// Fold the shared input embedding (W_in, b_in) into each LSTM's input weights.
// gate_k = sum_m x_m * Weff[k][m] + beff[k] + sum_j h_j * W_hh[k][j]
__global__ void fuse_kernel(const float* __restrict__ W_in, const float* __restrict__ b_in,
                            const float* __restrict__ W_ih_obs, const float* __restrict__ W_hh_obs,
                            const float* __restrict__ b_ih_obs, const float* __restrict__ b_hh_obs,
                            const float* __restrict__ W_ih_pre, const float* __restrict__ W_hh_pre,
                            const float* __restrict__ b_ih_pre, const float* __restrict__ b_hh_pre) {
    int k = threadIdx.x;
    if (k >= 64) return;
    int l = k >> 5, g = k & 31;
    const float* W_ih = l ? W_ih_pre : W_ih_obs;
    const float* W_hh = l ? W_hh_pre : W_hh_obs;
    const float* b_ih = l ? b_ih_pre : b_ih_obs;
    const float* b_hh = l ? b_hh_pre : b_hh_obs;

    float w0 = 0.f, w1 = 0.f, bb = 0.f;
    #pragma unroll
    for (int e = 0; e < 16; e++) {
        float wie = W_ih[g * 16 + e];
        w0 += wie * W_in[e * 2 + 0];
        w1 += wie * W_in[e * 2 + 1];
        bb += wie * b_in[e];
    }
    bb += b_ih[g] + b_hh[g];

    u64* o = g_fw + (l * GATES + g) * WSTRIDE;
    o[0] = dupf(w0);
    o[1] = dupf(w1);
    o[2] = dupf(bb);
    o[3] = 0ull;
    #pragma unroll
    for (int j = 0; j < HID; j++) o[4 + j] = dupf(W_hh[g * HID + j]);
}

// ---------------- packed f32x2 helpers ----------------
__device__ __forceinline__ u64 pk2(float lo, float hi) {
    u64 r; asm("mov.b64 %0, {%1,%2};" : "=l"(r) : "f"(lo), "f"(hi)); return r;
}
__device__ __forceinline__ void upk2(u64 v, float& lo, float& hi) {
    asm("mov.b64 {%0,%1}, %2;" : "=f"(lo), "=f"(hi) : "l"(v));
}
__device__ __forceinline__ u64 fma2(u64 a, u64 b, u64 c) {
    u64 d; asm("fma.rn.f32x2 %0, %1, %2, %3;" : "=l"(d) : "l"(a), "l"(b), "l"(c)); return d;
}

// Accurate activations: ex2.approx + rcp.approx -> ~1e-6 rel error
__device__ __forceinline__ float sigm(float x) {
    return __fdividef(1.0f, 1.0f + __expf(-x));
}
__device__ __forceinline__ float tanh_(float x) {
    return __fdividef(2.0f, 1.0f + __expf(-2.0f * x)) - 1.0f;
}

// One LSTM scan over T steps, processing a PAIR of batch elements (b0, b0+1)
// packed as f32x2 in every state/gate register.
template <int T>
__device__ __forceinline__ void run_lstm(const float* __restrict__ x, const u64* __restrict__ sw,
                                         u64 h[HID], u64 c[HID], int b0) {
    #pragma unroll 1
    for (int t = 0; t < T; t++) {
        // x[t, b0, 0..1], x[t, b0+1, 0..1] -> one float4 (16B aligned since b0 even)
        float4 xq = *(const float4*)(x + (size_t)t * (BATCH * 2) + (size_t)b0 * 2);
        u64 xa = pk2(xq.x, xq.z);   // {x0[b0], x0[b0+1]}
        u64 xb = pk2(xq.y, xq.w);   // {x1[b0], x1[b0+1]}

        u64 hn[HID];
        #pragma unroll
        for (int j = 0; j < HID; j++) {
            u64 acc[4];
            #pragma unroll
            for (int q = 0; q < 4; q++) {           // q: 0=i, 1=f, 2=g, 3=o (gate row q*8+j)
                const u64* wp = sw + (q * HID + j) * WSTRIDE;
                u64 a = fma2(xa, wp[0], wp[2]);     // bias as accumulator init
                a = fma2(xb, wp[1], a);
                #pragma unroll
                for (int jj = 0; jj < HID; jj++)
                    a = fma2(h[jj], wp[4 + jj], a);
                acc[q] = a;
            }
            float i0, i1, f0, f1, g0, g1, o0, o1, cv0, cv1;
            upk2(acc[0], i0, i1);
            upk2(acc[1], f0, f1);
            upk2(acc[2], g0, g1);
            upk2(acc[3], o0, o1);
            upk2(c[j], cv0, cv1);
            cv0 = sigm(f0) * cv0 + sigm(i0) * tanh_(g0);
            cv1 = sigm(f1) * cv1 + sigm(i1) * tanh_(g1);
            float hv0 = sigm(o0) * tanh_(cv0);
            float hv1 = sigm(o1) * tanh_(cv1);
            c[j]  = pk2(cv0, cv1);
            hn[j] = pk2(hv0, hv1);
        }
        #pragma unroll
        for (int j = 0; j < HID; j++) h[j] = hn[j];
    }
}

__device__ __forceinline__ void load_state_pair(const float* __restrict__ src, int b0, u64 dst[HID]) {
    const float4* p = (const float4*)(src + (size_t)b0 * HID);
    float4 a0 = p[0], a1 = p[1];   // element b0   : j 0..3, 4..7
    float4 b0v = p[2], b1v = p[3]; // element b0+1 : j 0..3, 4..7
    dst[0] = pk2(a0.x, b0v.x); dst[1] = pk2(a0.y, b0v.y);
    dst[2] = pk2(a0.z, b0v.z); dst[3] = pk2(a0.w, b0v.w);
    dst[4] = pk2(a1.x, b1v.x); dst[5] = pk2(a1.y, b1v.y);
    dst[6] = pk2(a1.z, b1v.z); dst[7] = pk2(a1.w, b1v.w);
}

__device__ __forceinline__ void store_h_pair(float* __restrict__ dst, int b0, const u64 h[HID]) {
    #pragma unroll
    for (int j = 0; j < HID; j++) {
        float lo, hi; upk2(h[j], lo, hi);
        // out flat layout is transpose(h): out[j*BATCH + b] = h[b][j]
        *(float2*)(dst + (size_t)j * BATCH + b0) = make_float2(lo, hi);
    }
}

__global__ void __launch_bounds__(256) lstm_main(
    const float* __restrict__ obs, const float* __restrict__ pre,
    const float* __restrict__ h0, const float* __restrict__ c0,
    const float* __restrict__ c0p, float* __restrict__ out) {
    __shared__ u64 sw[TOT_U64];
    for (int i = threadIdx.x; i < TOT_U64; i += 256) sw[i] = g_fw[i];
    __syncthreads();

    int tid = blockIdx.x * 256 + threadIdx.x;
    int b0 = tid * 2;

    u64 h[HID], c[HID];
    load_state_pair(h0, b0, h);
    load_state_pair(c0, b0, c);

    run_lstm<T_OBS>(obs, sw, h, c, b0);
    store_h_pair(out, b0, h);                       // c_out

    load_state_pair(c0p, b0, c);                    // cell re-initialized; h carries over
    run_lstm<T_PRE>(pre, sw + LSTM_U64, h, c, b0);
    store_h_pair(out + (size_t)BATCH * HID, b0, h); // x_out
}

extern "C" void kernel_launch(void* const* d_in, const int* in_sizes, int n_in,
                              void* d_out, int out_size) {
    const float* obs = (const float*)d_in[0];
    const float* pre = (const float*)d_in[1];
    const float* h0  = (const float*)d_in[2];
    const float* c0  = (const float*)d_in[3];
    const float* c0p = (const float*)d_in[4];

    fuse_kernel<<<1, 64>>>(
        (const float*)d_in[5],  (const float*)d_in[6],
        (const float*)d_in[7],  (const float*)d_in[8],
        (const float*)d_in[9],  (const float*)d_in[10],
        (const float*)d_in[11], (const float*)d_in[12],
        (const float*)d_in[13], (const float*)d_in[14]);

    lstm_main<<<(BATCH / 2) / 256, 256>>>(obs, pre, h0, c0, c0p, (float*)d_out);
}

// round 3
// speedup vs baseline: 3.0722x; 3.0722x over previous
#include <cuda_runtime.h>

#define T_OBS   8
#define T_PRE   12
#define BATCH   524288
#define HID     8
#define GATES   32
#define WSTRIDE 12                    // floats per gate: w0, w1, b, pad, whh[0..7]
#define LSTM_F  (GATES * WSTRIDE)     // 384
#define TOT_F   (2 * LSTM_F)          // 768

// Fused weights (embedding folded into input weights): [lstm][gate][12]
__device__ float g_fw[TOT_F];

// Fold shared input embedding (W_in, b_in) into each LSTM's input weights:
// gate_k = x0*Weff[k][0] + x1*Weff[k][1] + beff[k] + sum_j h_j*W_hh[k][j]
__global__ void fuse_kernel(const float* __restrict__ W_in, const float* __restrict__ b_in,
                            const float* __restrict__ W_ih_obs, const float* __restrict__ W_hh_obs,
                            const float* __restrict__ b_ih_obs, const float* __restrict__ b_hh_obs,
                            const float* __restrict__ W_ih_pre, const float* __restrict__ W_hh_pre,
                            const float* __restrict__ b_ih_pre, const float* __restrict__ b_hh_pre) {
    int k = threadIdx.x;
    if (k >= 64) return;
    int l = k >> 5, g = k & 31;
    const float* W_ih = l ? W_ih_pre : W_ih_obs;
    const float* W_hh = l ? W_hh_pre : W_hh_obs;
    const float* b_ih = l ? b_ih_pre : b_ih_obs;
    const float* b_hh = l ? b_hh_pre : b_hh_obs;

    float w0 = 0.f, w1 = 0.f, bb = 0.f;
    #pragma unroll
    for (int e = 0; e < 16; e++) {
        float wie = W_ih[g * 16 + e];
        w0 += wie * W_in[e * 2 + 0];
        w1 += wie * W_in[e * 2 + 1];
        bb += wie * b_in[e];
    }
    bb += b_ih[g] + b_hh[g];

    float* o = g_fw + (l * GATES + g) * WSTRIDE;
    o[0] = w0; o[1] = w1; o[2] = bb; o[3] = 0.f;
    #pragma unroll
    for (int j = 0; j < HID; j++) o[4 + j] = W_hh[g * HID + j];
}

// Accurate-enough activations: ex2.approx + rcp.approx (~1e-7 rel)
__device__ __forceinline__ float sigm(float x) {
    return __fdividef(1.0f, 1.0f + __expf(-x));
}
__device__ __forceinline__ float tanh_(float x) {
    return __fdividef(2.0f, 1.0f + __expf(-2.0f * x)) - 1.0f;
}

// One LSTM scan over T steps for a single batch element b.
template <int T>
__device__ __forceinline__ void run_lstm(const float* __restrict__ x,
                                         const float* __restrict__ sw,
                                         float h[HID], float c[HID], int b) {
    // prefetch t=0
    float2 xv = *(const float2*)(x + (size_t)b * 2);

    #pragma unroll 1
    for (int t = 0; t < T; t++) {
        float2 xn;
        if (t + 1 < T)
            xn = *(const float2*)(x + (size_t)(t + 1) * (BATCH * 2) + (size_t)b * 2);

        float hn[HID];
        #pragma unroll
        for (int j = 0; j < HID; j++) {
            float acc[4];
            #pragma unroll
            for (int q = 0; q < 4; q++) {          // gate rows: i=j, f=8+j, g=16+j, o=24+j
                const float* w = sw + (q * HID + j) * WSTRIDE;
                float a = fmaf(xv.x, w[0], w[2]);
                a = fmaf(xv.y, w[1], a);
                #pragma unroll
                for (int jj = 0; jj < HID; jj++)
                    a = fmaf(h[jj], w[4 + jj], a);
                acc[q] = a;
            }
            float cn = sigm(acc[1]) * c[j] + sigm(acc[0]) * tanh_(acc[2]);
            c[j]  = cn;
            hn[j] = sigm(acc[3]) * tanh_(cn);
        }
        #pragma unroll
        for (int j = 0; j < HID; j++) h[j] = hn[j];
        xv = xn;
    }
}

__device__ __forceinline__ void load_state(const float* __restrict__ src, int b, float d[HID]) {
    const float4* p = (const float4*)(src + (size_t)b * HID);
    float4 a = p[0], v = p[1];
    d[0] = a.x; d[1] = a.y; d[2] = a.z; d[3] = a.w;
    d[4] = v.x; d[5] = v.y; d[6] = v.z; d[7] = v.w;
}

__device__ __forceinline__ void store_h(float* __restrict__ dst, int b, const float h[HID]) {
    // out layout is transpose(h): out[j*BATCH + b] = h[b][j]  (coalesced across threads)
    #pragma unroll
    for (int j = 0; j < HID; j++)
        dst[(size_t)j * BATCH + b] = h[j];
}

__global__ void __launch_bounds__(256) lstm_main(
    const float* __restrict__ obs, const float* __restrict__ pre,
    const float* __restrict__ h0, const float* __restrict__ c0,
    const float* __restrict__ c0p, float* __restrict__ out) {
    __shared__ float sw[TOT_F];
    for (int i = threadIdx.x; i < TOT_F; i += 256) sw[i] = g_fw[i];
    __syncthreads();

    int b = blockIdx.x * 256 + threadIdx.x;

    float h[HID], c[HID];
    load_state(h0, b, h);
    load_state(c0, b, c);

    run_lstm<T_OBS>(obs, sw, h, c, b);
    store_h(out, b, h);                              // c_out

    load_state(c0p, b, c);                           // cell re-init; h carries over
    run_lstm<T_PRE>(pre, sw + LSTM_F, h, c, b);
    store_h(out + (size_t)BATCH * HID, b, h);        // x_out
}

extern "C" void kernel_launch(void* const* d_in, const int* in_sizes, int n_in,
                              void* d_out, int out_size) {
    const float* obs = (const float*)d_in[0];
    const float* pre = (const float*)d_in[1];
    const float* h0  = (const float*)d_in[2];
    const float* c0  = (const float*)d_in[3];
    const float* c0p = (const float*)d_in[4];

    fuse_kernel<<<1, 64>>>(
        (const float*)d_in[5],  (const float*)d_in[6],
        (const float*)d_in[7],  (const float*)d_in[8],
        (const float*)d_in[9],  (const float*)d_in[10],
        (const float*)d_in[11], (const float*)d_in[12],
        (const float*)d_in[13], (const float*)d_in[14]);

    lstm_main<<<BATCH / 256, 256>>>(obs, pre, h0, c0, c0p, (float*)d_out);
}